// round 6
// baseline (speedup 1.0000x reference)
#include <cuda_runtime.h>
#include <cuda_fp16.h>
#include <math.h>
#include <stdint.h>

// Problem dims
#define L_ 12
#define B_ 2
#define T_ 1024
#define D_ 1024
#define H_ 16
#define HD_ 64
#define F_ 4096
#define V_ 50257
#define VPAD_ 50304
#define BT_ (B_*T_)

// ================= scratch (__device__ globals) =================
__device__ float g_x  [BT_*D_];
__device__ float g_qkv[BT_*3072];
__device__ float g_att[(size_t)B_*H_*T_*T_];

__device__ __align__(256) __half g_hh [BT_*D_];
__device__ __align__(256) __half g_hl [BT_*D_];
__device__ __align__(256) __half g_obh[BT_*D_];
__device__ __align__(256) __half g_obl[BT_*D_];
__device__ __align__(256) __half g_mph[BT_*F_];
__device__ __align__(256) __half g_mpl[BT_*F_];

// attention operands
__device__ __align__(256) __half g_qTh[BT_*D_];
__device__ __align__(256) __half g_qTl[BT_*D_];
__device__ __align__(256) __half g_kTh[BT_*D_];          // K single fp16
__device__ __align__(256) __half g_vTh[BT_*D_];          // V single fp16, [B,H,HD,T]
__device__ __align__(256) __half g_ph [(size_t)B_*H_*T_*T_];
__device__ __align__(256) __half g_pl [(size_t)B_*H_*T_*T_];

// converted+transposed weights [N,K] layout, single fp16
__device__ __align__(256) __half g_wqkv[(size_t)L_*3072*D_];
__device__ __align__(256) __half g_wo  [(size_t)L_*D_*D_];
__device__ __align__(256) __half g_w1  [(size_t)L_*F_*D_];
__device__ __align__(256) __half g_w2  [(size_t)L_*D_*F_];
__device__ __align__(256) __half g_wlm [(size_t)VPAD_*D_];

// ================= small helpers =================
__device__ __forceinline__ uint32_t smem_u32(const void* p) {
    uint32_t a;
    asm("{ .reg .u64 t; cvta.to.shared.u64 t, %1; cvt.u32.u64 %0, t; }" : "=r"(a) : "l"(p));
    return a;
}
__device__ __forceinline__ void fp16_split(float v, __half& hi, __half& lo) {
    hi = __float2half(v);
    lo = __float2half(v - __half2float(hi));
}

// ================= elementwise / conversion kernels =================
__global__ void embed_kernel(const int* __restrict__ ids, const float* __restrict__ emb,
                             const float* __restrict__ pos, float* __restrict__ x) {
    int idx = blockIdx.x * 256 + threadIdx.x;
    int row = idx >> 10;
    int c   = idx & 1023;
    int t   = row & (T_-1);
    x[idx] = emb[(size_t)ids[row]*D_ + c] + pos[(size_t)t*D_ + c];
}

// W [K,N] fp32 -> out [Npad,K] fp16 (transposed, zero-padded), batched over z
__global__ void wconv_kernel(const float* __restrict__ W, __half* __restrict__ oh,
                             int K, int N, long long srcStride, long long dstStride) {
    __shared__ float tile[32][33];
    const float* Ws = W + (size_t)blockIdx.z * srcStride;
    __half* ohz = oh + (size_t)blockIdx.z * dstStride;
    int n0 = blockIdx.x * 32, k0 = blockIdx.y * 32;
    #pragma unroll
    for (int j = 0; j < 32; j += 8) {
        int kk = k0 + threadIdx.y + j;
        int nn = n0 + threadIdx.x;
        tile[threadIdx.y + j][threadIdx.x] = (nn < N) ? Ws[(size_t)kk*N + nn] : 0.f;
    }
    __syncthreads();
    #pragma unroll
    for (int j = 0; j < 32; j += 8) {
        int nn = n0 + threadIdx.y + j;
        int kk = k0 + threadIdx.x;
        ohz[(size_t)nn*K + kk] = __float2half(tile[threadIdx.x][threadIdx.y + j]);
    }
}

// Wq/Wk/Wv [L][K,N] fp32 -> g_wqkv [L][3072,K] fp16, z in [0, 3L)
__global__ void wconv3_kernel(const float* __restrict__ Wq, const float* __restrict__ Wk,
                              const float* __restrict__ Wv, __half* __restrict__ dst) {
    __shared__ float tile[32][33];
    int z = blockIdx.z;
    int l = z / 3, sel = z % 3;
    const float* Ws = (sel == 0 ? Wq : sel == 1 ? Wk : Wv) + (size_t)l * D_ * D_;
    __half* od = dst + ((size_t)l * 3072 + sel * D_) * D_;
    int n0 = blockIdx.x * 32, k0 = blockIdx.y * 32;
    #pragma unroll
    for (int j = 0; j < 32; j += 8) {
        tile[threadIdx.y + j][threadIdx.x] = Ws[(size_t)(k0 + threadIdx.y + j)*D_ + n0 + threadIdx.x];
    }
    __syncthreads();
    #pragma unroll
    for (int j = 0; j < 32; j += 8) {
        int nn = n0 + threadIdx.y + j;
        int kk = k0 + threadIdx.x;
        od[(size_t)nn*D_ + kk] = __float2half(tile[threadIdx.x][threadIdx.y + j]);
    }
}

__global__ void rmsnorm_split_kernel(const float* __restrict__ x, const float* __restrict__ w,
                                     __half* __restrict__ oh, __half* __restrict__ ol) {
    __shared__ float red[256];
    int row = blockIdx.x;
    const float* xr = x + (size_t)row * D_;
    float v[4]; float ss = 0.f;
    #pragma unroll
    for (int i = 0; i < 4; i++) { v[i] = xr[threadIdx.x + 256*i]; ss += v[i]*v[i]; }
    red[threadIdx.x] = ss; __syncthreads();
    for (int s = 128; s > 0; s >>= 1) {
        if (threadIdx.x < s) red[threadIdx.x] += red[threadIdx.x + s];
        __syncthreads();
    }
    float r = rsqrtf(red[0] / (float)D_ + 1e-5f);
    #pragma unroll
    for (int i = 0; i < 4; i++) {
        int c = threadIdx.x + 256*i;
        float y = w[c] * v[i] * r;
        __half hi, lo; fp16_split(y, hi, lo);
        oh[(size_t)row*D_ + c] = hi;
        ol[(size_t)row*D_ + c] = lo;
    }
}

// RMS over head_dim + transpose [B,T,3D] -> [B,H,T,HD] fp16 (lo optional). One warp per (b,t,h).
__global__ void qknorm_split_kernel(const float* __restrict__ qkv, int colOff,
                                    const float* __restrict__ w,
                                    __half* __restrict__ qh, __half* __restrict__ ql) {
    int warp = (blockIdx.x * blockDim.x + threadIdx.x) >> 5;
    int lane = threadIdx.x & 31;
    int h  = warp & (H_-1);
    int bt = warp >> 4;
    int t  = bt & (T_-1);
    int b  = bt >> 10;
    const float* src = qkv + (size_t)bt * 3072 + colOff + h * HD_;
    float x0 = src[lane], x1 = src[lane + 32];
    float ss = x0*x0 + x1*x1;
    #pragma unroll
    for (int o = 16; o > 0; o >>= 1) ss += __shfl_xor_sync(0xffffffffu, ss, o);
    float r = rsqrtf(ss / (float)HD_ + 1e-5f);
    size_t dst = ((size_t)((b*H_ + h)*T_ + t)) * HD_;
    float y0 = w[lane] * x0 * r;
    float y1 = w[lane + 32] * x1 * r;
    __half h0 = __float2half(y0);
    __half h1 = __float2half(y1);
    qh[dst + lane]      = h0;
    qh[dst + lane + 32] = h1;
    if (ql) {
        ql[dst + lane]      = __float2half(y0 - __half2float(h0));
        ql[dst + lane + 32] = __float2half(y1 - __half2float(h1));
    }
}

// V: [B,T,3D](col 2048+) -> [B,H,HD,T] single fp16 via 32x32 tile transpose
__global__ void vtrans_kernel(const float* __restrict__ qkv, __half* __restrict__ vh) {
    __shared__ float tile[32][33];
    int z = blockIdx.z;           // b*H+h
    int b = z >> 4, h = z & 15;
    int t0 = blockIdx.x * 32, d0 = blockIdx.y * 32;
    #pragma unroll
    for (int j = 0; j < 32; j += 8) {
        int t = t0 + threadIdx.y + j;
        tile[threadIdx.y + j][threadIdx.x] =
            qkv[(size_t)(b*T_ + t)*3072 + 2048 + h*HD_ + d0 + threadIdx.x];
    }
    __syncthreads();
    #pragma unroll
    for (int j = 0; j < 32; j += 8) {
        int d = d0 + threadIdx.y + j;
        size_t o = ((size_t)z * HD_ + d) * T_ + t0 + threadIdx.x;
        vh[o] = __float2half(tile[threadIdx.x][threadIdx.y + j]);
    }
}

// causal softmax, scale 1/8, per-head gate; writes P as fp16 hi/lo (zero tail)
__global__ void softmax_kernel(const float* __restrict__ S, const float* __restrict__ gate,
                               __half* __restrict__ ph, __half* __restrict__ pl) {
    __shared__ float red[256];
    int row = blockIdx.x;
    int q = row & (T_-1);
    int h = (row >> 10) & (H_-1);
    const float* s = S + (size_t)row * T_;
    const float scale = 0.125f;
    float vals[4]; float m = -3.4e38f;
    #pragma unroll
    for (int i = 0; i < 4; i++) {
        int j = threadIdx.x + 256*i;
        float v = (j <= q) ? s[j] * scale : -3.4e38f;
        vals[i] = v; m = fmaxf(m, v);
    }
    red[threadIdx.x] = m; __syncthreads();
    for (int t = 128; t > 0; t >>= 1) {
        if (threadIdx.x < t) red[threadIdx.x] = fmaxf(red[threadIdx.x], red[threadIdx.x + t]);
        __syncthreads();
    }
    m = red[0]; __syncthreads();
    float sum = 0.f;
    #pragma unroll
    for (int i = 0; i < 4; i++) {
        int j = threadIdx.x + 256*i;
        float e = (j <= q) ? __expf(vals[i] - m) : 0.f;
        vals[i] = e; sum += e;
    }
    red[threadIdx.x] = sum; __syncthreads();
    for (int t = 128; t > 0; t >>= 1) {
        if (threadIdx.x < t) red[threadIdx.x] += red[threadIdx.x + t];
        __syncthreads();
    }
    float inv = gate[h] / red[0];
    #pragma unroll
    for (int i = 0; i < 4; i++) {
        int j = threadIdx.x + 256*i;
        float p = vals[i] * inv;
        __half hi, lo; fp16_split(p, hi, lo);
        ph[(size_t)row*T_ + j] = hi;
        pl[(size_t)row*T_ + j] = lo;
    }
}

// ================= HMMA fp16 2-term split GEMM =================
// C[M,N] = (Ah+Al)[M,K] @ Bh[N,K]^T, fp32 accumulators.
// MODE: 0 = fp32 store (guard n<Nout), 1 = +RES, 2 = GELU->fp16 split, 3 = PV merge->fp16 split
#define HG_ROWB 80

__device__ __forceinline__ void hg_ldm4(uint32_t addr, uint32_t* r) {
    asm volatile("ldmatrix.sync.aligned.m8n8.x4.shared.b16 {%0,%1,%2,%3}, [%4];"
        : "=r"(r[0]), "=r"(r[1]), "=r"(r[2]), "=r"(r[3]) : "r"(addr));
}
__device__ __forceinline__ void hg_mma(float* d, const uint32_t* a, uint32_t b0, uint32_t b1) {
    asm volatile("mma.sync.aligned.m16n8k16.row.col.f32.f16.f16.f32 "
        "{%0,%1,%2,%3}, {%4,%5,%6,%7}, {%8,%9}, {%0,%1,%2,%3};"
        : "+f"(d[0]), "+f"(d[1]), "+f"(d[2]), "+f"(d[3])
        : "r"(a[0]), "r"(a[1]), "r"(a[2]), "r"(a[3]), "r"(b0), "r"(b1));
}

template<int BM, int BN>
__device__ __forceinline__ void hg_load2(uint32_t stg,
    const __half* Ah, const __half* Al, const __half* Bh,
    int m0, int n0, int K, int k0, int tid)
{
    constexpr int CA = BM * 4;         // 16B chunks per A matrix
    constexpr int CB = BN * 4;
    constexpr int TOT = 2*CA + CB;
    #pragma unroll
    for (int p = 0; p < TOT/256; p++) {
        int c = tid + p * 256;
        const __half* base; int r0; uint32_t mo; int rr;
        if (c < CA)        { base = Ah; r0 = m0; mo = 0;            rr = c; }
        else if (c < 2*CA) { base = Al; r0 = m0; mo = BM*HG_ROWB;   rr = c - CA; }
        else               { base = Bh; r0 = n0; mo = 2*BM*HG_ROWB; rr = c - 2*CA; }
        int r = rr >> 2, kc = rr & 3;
        uint32_t so = stg + mo + r * HG_ROWB + kc * 16;
        const void* ga = (const void*)(base + (size_t)(r0 + r) * K + k0 + kc * 8);
        asm volatile("cp.async.cg.shared.global [%0], [%1], 16;\n" :: "r"(so), "l"(ga));
    }
    asm volatile("cp.async.commit_group;\n" ::: "memory");
}

template<int BM, int BN, int MODE, bool CSKIP, bool CKLIM>
__global__ __launch_bounds__(256)
void hgemm2_kernel(const __half* __restrict__ Ah, const __half* __restrict__ Al,
                   const __half* __restrict__ Bh,
                   const float* __restrict__ AUX, float* __restrict__ C,
                   __half* __restrict__ Gh, __half* __restrict__ Gl,
                   int K, int Nout, int ldc,
                   long long sA, long long sB, long long sC)
{
    constexpr int MATA  = BM * HG_ROWB;
    constexpr int MATB  = BN * HG_ROWB;
    constexpr int STAGE = 2*MATA + MATB;
    constexpr int MI = BM / 64;        // 16-row A tiles per warp
    constexpr int NJ = BN / 16;        // 8-col accum groups per warp
    constexpr int NT = BN / 32;        // 16-row B tiles per warp

    extern __shared__ char dsm[];
    uint32_t sb = smem_u32(dsm);

    const int tid  = threadIdx.x;
    const int lane = tid & 31;
    const int wid  = tid >> 5;
    const int warpM = (wid & 3) * (BM/4);
    const int warpN = (wid >> 2) * (BN/2);

    const int m0 = blockIdx.y * BM;
    const int n0 = blockIdx.x * BN;
    if (CSKIP && n0 > m0 + BM - 1) return;

    const int z = blockIdx.z;
    Ah += (size_t)z * sA; Al += (size_t)z * sA;
    Bh += (size_t)z * sB;
    if (MODE == 0) C += (size_t)z * sC;

    const uint32_t aoff = (uint32_t)((lane & 15) * HG_ROWB + (lane >> 4) * 16);
    const uint32_t boff = (uint32_t)(((lane & 7) + ((lane >> 4) & 1) * 8) * HG_ROWB
                                     + ((lane >> 3) & 1) * 16);

    float acc[MI][NJ][4];
    #pragma unroll
    for (int i = 0; i < MI; i++)
        #pragma unroll
        for (int j = 0; j < NJ; j++)
            #pragma unroll
            for (int u = 0; u < 4; u++) acc[i][j][u] = 0.f;

    const int kend = CKLIM ? (K < m0 + BM ? K : m0 + BM) : K;
    const int nk = kend / 32;
    hg_load2<BM,BN>(sb, Ah, Al, Bh, m0, n0, K, 0, tid);

    for (int it = 0; it < nk; it++) {
        int s = it & 1;
        if (it + 1 < nk) {
            hg_load2<BM,BN>(sb + (1 - s) * STAGE, Ah, Al, Bh, m0, n0, K, (it + 1) * 32, tid);
            asm volatile("cp.async.wait_group 1;\n" ::: "memory");
        } else {
            asm volatile("cp.async.wait_group 0;\n" ::: "memory");
        }
        __syncthreads();

        uint32_t st  = sb + s * STAGE;
        uint32_t sAh = st;
        uint32_t sAl = st + MATA;
        uint32_t sBh = st + 2*MATA;

        #pragma unroll
        for (int kq = 0; kq < 2; kq++) {
            uint32_t kb = kq * 32;
            uint32_t ah[MI][4], al[MI][4], bh[NT][4];
            #pragma unroll
            for (int mi = 0; mi < MI; mi++) {
                uint32_t rb = (uint32_t)((warpM + mi * 16) * HG_ROWB) + kb;
                hg_ldm4(sAh + rb + aoff, ah[mi]);
                hg_ldm4(sAl + rb + aoff, al[mi]);
            }
            #pragma unroll
            for (int nt = 0; nt < NT; nt++) {
                uint32_t rb = (uint32_t)((warpN + nt * 16) * HG_ROWB) + kb;
                hg_ldm4(sBh + rb + boff, bh[nt]);
            }
            #pragma unroll
            for (int mi = 0; mi < MI; mi++) {
                #pragma unroll
                for (int nj = 0; nj < NJ; nj++) {
                    uint32_t b0 = bh[nj >> 1][(nj & 1) * 2];
                    uint32_t b1 = bh[nj >> 1][(nj & 1) * 2 + 1];
                    hg_mma(acc[mi][nj], ah[mi], b0, b1);
                    hg_mma(acc[mi][nj], al[mi], b0, b1);
                }
            }
        }
        __syncthreads();
    }

    // epilogue
    const int g = lane >> 2;
    const int tq = lane & 3;
    #pragma unroll
    for (int mi = 0; mi < MI; mi++) {
        int row0 = m0 + warpM + mi * 16 + g;
        int row1 = row0 + 8;
        #pragma unroll
        for (int nj = 0; nj < NJ; nj++) {
            int col = n0 + warpN + nj * 8 + tq * 2;
            float* a = acc[mi][nj];
            if (MODE == 1) {
                size_t o0 = (size_t)row0 * ldc + col;
                size_t o1 = (size_t)row1 * ldc + col;
                C[o0]     = a[0] + AUX[o0];
                C[o0 + 1] = a[1] + AUX[o0 + 1];
                C[o1]     = a[2] + AUX[o1];
                C[o1 + 1] = a[3] + AUX[o1 + 1];
            } else if (MODE == 2) {
                #pragma unroll
                for (int half = 0; half < 2; half++) {
                    int r = half ? row1 : row0;
                    float v0 = a[half * 2], v1 = a[half * 2 + 1];
                    float g0 = 0.5f * v0 * (1.0f + erff(v0 * 0.70710678118654752f));
                    float g1 = 0.5f * v1 * (1.0f + erff(v1 * 0.70710678118654752f));
                    __half h0, l0, h1, l1;
                    fp16_split(g0, h0, l0); fp16_split(g1, h1, l1);
                    __half2 hp; hp.x = h0; hp.y = h1;
                    __half2 lp; lp.x = l0; lp.y = l1;
                    size_t o = (size_t)r * ldc + col;
                    *(__half2*)&Gh[o] = hp;
                    *(__half2*)&Gl[o] = lp;
                }
            } else if (MODE == 3) {
                int b  = z >> 4, h = z & 15;
                #pragma unroll
                for (int half = 0; half < 2; half++) {
                    int q = half ? row1 : row0;
                    size_t vsrc = (size_t)(b*T_ + q)*3072 + 2048 + h*HD_ + col;
                    float v0 = a[half * 2]     + AUX[vsrc];
                    float v1 = a[half * 2 + 1] + AUX[vsrc + 1];
                    __half h0, l0, h1, l1;
                    fp16_split(v0, h0, l0); fp16_split(v1, h1, l1);
                    __half2 hp; hp.x = h0; hp.y = h1;
                    __half2 lp; lp.x = l0; lp.y = l1;
                    size_t o = (size_t)(b*T_ + q)*D_ + h*HD_ + col;
                    *(__half2*)&Gh[o] = hp;
                    *(__half2*)&Gl[o] = lp;
                }
            } else {
                if (col < Nout) {
                    C[(size_t)row0 * ldc + col] = a[0];
                    C[(size_t)row1 * ldc + col] = a[2];
                }
                if (col + 1 < Nout) {
                    C[(size_t)row0 * ldc + col + 1] = a[1];
                    C[(size_t)row1 * ldc + col + 1] = a[3];
                }
            }
        }
    }
}

// ================= launcher =================
extern "C" void kernel_launch(void* const* d_in, const int* in_sizes, int n_in,
                              void* d_out, int out_size) {
    const int*   ids   = (const int*)  d_in[0];
    const float* embed = (const float*)d_in[1];
    const float* pos   = (const float*)d_in[2];
    const float* Wq    = (const float*)d_in[3];
    const float* Wk    = (const float*)d_in[4];
    const float* Wv    = (const float*)d_in[5];
    const float* Wo    = (const float*)d_in[6];
    const float* ln1   = (const float*)d_in[7];
    const float* ln2   = (const float*)d_in[8];
    const float* qnw   = (const float*)d_in[9];
    const float* knw   = (const float*)d_in[10];
    const float* gate  = (const float*)d_in[11];
    const float* W1    = (const float*)d_in[12];
    const float* W2    = (const float*)d_in[13];
    const float* lnf   = (const float*)d_in[14];
    const float* Wlm   = (const float*)d_in[15];
    float* out = (float*)d_out;

    float *x,*qkv,*att;
    __half *hh,*hl,*obh,*obl,*mph,*mpl;
    __half *qTh,*qTl,*kTh,*vTh,*ph,*pl;
    __half *wqkv,*wo,*w1,*w2,*wlm;
    cudaGetSymbolAddress((void**)&x,   g_x);
    cudaGetSymbolAddress((void**)&qkv, g_qkv);
    cudaGetSymbolAddress((void**)&att, g_att);
    cudaGetSymbolAddress((void**)&hh,  g_hh);
    cudaGetSymbolAddress((void**)&hl,  g_hl);
    cudaGetSymbolAddress((void**)&obh, g_obh);
    cudaGetSymbolAddress((void**)&obl, g_obl);
    cudaGetSymbolAddress((void**)&mph, g_mph);
    cudaGetSymbolAddress((void**)&mpl, g_mpl);
    cudaGetSymbolAddress((void**)&qTh, g_qTh);
    cudaGetSymbolAddress((void**)&qTl, g_qTl);
    cudaGetSymbolAddress((void**)&kTh, g_kTh);
    cudaGetSymbolAddress((void**)&vTh, g_vTh);
    cudaGetSymbolAddress((void**)&ph,  g_ph);
    cudaGetSymbolAddress((void**)&pl,  g_pl);
    cudaGetSymbolAddress((void**)&wqkv, g_wqkv);
    cudaGetSymbolAddress((void**)&wo,  g_wo);
    cudaGetSymbolAddress((void**)&w1,  g_w1);
    cudaGetSymbolAddress((void**)&w2,  g_w2);
    cudaGetSymbolAddress((void**)&wlm, g_wlm);

    const int SM128 = 2 * (2*128 + 128) * HG_ROWB;   // 61440
    const int SM64  = 2 * (2*64  + 64 ) * HG_ROWB;   // 30720
    cudaFuncSetAttribute(hgemm2_kernel<128,128,0,false,false>, cudaFuncAttributeMaxDynamicSharedMemorySize, SM128);
    cudaFuncSetAttribute(hgemm2_kernel<128,128,1,false,false>, cudaFuncAttributeMaxDynamicSharedMemorySize, SM128);
    cudaFuncSetAttribute(hgemm2_kernel<128,128,2,false,false>, cudaFuncAttributeMaxDynamicSharedMemorySize, SM128);
    cudaFuncSetAttribute(hgemm2_kernel<128,128,0,true, false>, cudaFuncAttributeMaxDynamicSharedMemorySize, SM128);
    cudaFuncSetAttribute(hgemm2_kernel<64, 64, 3,false,true >, cudaFuncAttributeMaxDynamicSharedMemorySize, SM64);

    const long long sQK = (long long)T_ * HD_;
    const long long sS  = (long long)T_ * T_;
    dim3 wb(32, 8);

    // Order: embed, rmsnorm(l0), wconv3, QKV-gemm(l0) early so ncu catches hgemm2
    embed_kernel<<<BT_*D_/256, 256>>>(ids, embed, pos, x);
    rmsnorm_split_kernel<<<BT_, 256>>>(x, ln1, hh, hl);
    wconv3_kernel<<<dim3(D_/32, D_/32, 3*L_), wb>>>(Wq, Wk, Wv, wqkv);
    hgemm2_kernel<128,128,0,false,false><<<dim3(3072/128, BT_/128), 256, SM128>>>(
        hh, hl, wqkv, nullptr, qkv, nullptr, nullptr, D_, 3072, 3072, 0, 0, 0);

    // remaining weight conversions
    wconv_kernel<<<dim3(D_/32, D_/32, L_), wb>>>(Wo, wo, D_, D_, (long long)D_*D_, (long long)D_*D_);
    wconv_kernel<<<dim3(F_/32, D_/32, L_), wb>>>(W1, w1, D_, F_, (long long)D_*F_, (long long)F_*D_);
    wconv_kernel<<<dim3(D_/32, F_/32, L_), wb>>>(W2, w2, F_, D_, (long long)F_*D_, (long long)D_*F_);
    wconv_kernel<<<dim3(VPAD_/32, D_/32, 1), wb>>>(Wlm, wlm, D_, V_, 0, 0);

    for (int l = 0; l < L_; l++) {
        qknorm_split_kernel<<<(B_*T_*H_)/8, 256>>>(qkv, 0,    qnw + (size_t)l*HD_, qTh, qTl);
        qknorm_split_kernel<<<(B_*T_*H_)/8, 256>>>(qkv, 1024, knw + (size_t)l*HD_, kTh, nullptr);
        vtrans_kernel<<<dim3(T_/32, HD_/32, B_*H_), dim3(32,8)>>>(qkv, vTh);

        // scores: per (b,h) Q[1024,64] @ K[1024,64]^T, causal tile-skip
        hgemm2_kernel<128,128,0,true,false><<<dim3(T_/128, T_/128, B_*H_), 256, SM128>>>(
            qTh, qTl, kTh, nullptr, att, nullptr, nullptr, HD_, T_, T_, sQK, sQK, sS);

        softmax_kernel<<<B_*H_*T_, 256>>>(att, gate + (size_t)l*H_, ph, pl);

        // PV: per (b,h) P[1024,1024] @ V^T, causal K-limit, fused vres merge+split
        hgemm2_kernel<64,64,3,false,true><<<dim3(1, T_/64, B_*H_), 256, SM64>>>(
            ph, pl, vTh, qkv, nullptr, obh, obl, T_, HD_, HD_, sS, sQK, 0);

        // Wo with fused residual into x
        hgemm2_kernel<128,128,1,false,false><<<dim3(D_/128, BT_/128), 256, SM128>>>(
            obh, obl, wo + (size_t)l*D_*D_, x, x, nullptr, nullptr, D_, D_, D_, 0, 0, 0);

        // MLP
        rmsnorm_split_kernel<<<BT_, 256>>>(x, ln2 + (size_t)l*D_, hh, hl);
        hgemm2_kernel<128,128,2,false,false><<<dim3(F_/128, BT_/128), 256, SM128>>>(
            hh, hl, w1 + (size_t)l*F_*D_, nullptr, nullptr, mph, mpl, D_, F_, F_, 0, 0, 0);
        hgemm2_kernel<128,128,1,false,false><<<dim3(D_/128, BT_/128), 256, SM128>>>(
            mph, mpl, w2 + (size_t)l*D_*F_, x, x, nullptr, nullptr, F_, D_, D_, 0, 0, 0);

        // next layer's pre-attention norm + QKV
        if (l + 1 < L_) {
            rmsnorm_split_kernel<<<BT_, 256>>>(x, ln1 + (size_t)(l+1)*D_, hh, hl);
            hgemm2_kernel<128,128,0,false,false><<<dim3(3072/128, BT_/128), 256, SM128>>>(
                hh, hl, wqkv + (size_t)(l+1)*3072*D_, nullptr, qkv, nullptr, nullptr,
                D_, 3072, 3072, 0, 0, 0);
        }
    }

    rmsnorm_split_kernel<<<BT_, 256>>>(x, lnf, hh, hl);
    hgemm2_kernel<128,128,0,false,false><<<dim3(VPAD_/128, BT_/128), 256, SM128>>>(
        hh, hl, wlm, nullptr, out, nullptr, nullptr, D_, V_, V_, 0, 0, 0);
}

// round 7
// speedup vs baseline: 1.0290x; 1.0290x over previous
#include <cuda_runtime.h>
#include <cuda_fp16.h>
#include <math.h>
#include <stdint.h>

// Problem dims
#define L_ 12
#define B_ 2
#define T_ 1024
#define D_ 1024
#define H_ 16
#define HD_ 64
#define F_ 4096
#define V_ 50257
#define VPAD_ 50304
#define BT_ (B_*T_)

// ================= scratch (__device__ globals) =================
__device__ float g_x  [BT_*D_];
__device__ float g_qkv[BT_*3072];
__device__ float g_att[(size_t)B_*H_*T_*T_];

__device__ __align__(256) __half g_hh [BT_*D_];
__device__ __align__(256) __half g_hl [BT_*D_];
__device__ __align__(256) __half g_obh[BT_*D_];
__device__ __align__(256) __half g_obl[BT_*D_];
__device__ __align__(256) __half g_mph[BT_*F_];
__device__ __align__(256) __half g_mpl[BT_*F_];

// attention operands
__device__ __align__(256) __half g_qTh[BT_*D_];
__device__ __align__(256) __half g_qTl[BT_*D_];
__device__ __align__(256) __half g_kTh[BT_*D_];          // K single fp16
__device__ __align__(256) __half g_vTh[BT_*D_];          // V single fp16, [B,H,HD,T]
__device__ __align__(256) __half g_ph [(size_t)B_*H_*T_*T_];
__device__ __align__(256) __half g_pl [(size_t)B_*H_*T_*T_];

// converted+transposed weights [N,K] layout, single fp16
__device__ __align__(256) __half g_wqkv[(size_t)L_*3072*D_];
__device__ __align__(256) __half g_wo  [(size_t)L_*D_*D_];
__device__ __align__(256) __half g_w1  [(size_t)L_*F_*D_];
__device__ __align__(256) __half g_w2  [(size_t)L_*D_*F_];
__device__ __align__(256) __half g_wlm [(size_t)VPAD_*D_];

// ================= small helpers =================
__device__ __forceinline__ uint32_t smem_u32(const void* p) {
    uint32_t a;
    asm("{ .reg .u64 t; cvta.to.shared.u64 t, %1; cvt.u32.u64 %0, t; }" : "=r"(a) : "l"(p));
    return a;
}
__device__ __forceinline__ void fp16_split(float v, __half& hi, __half& lo) {
    hi = __float2half(v);
    lo = __float2half(v - __half2float(hi));
}

// ================= elementwise / conversion kernels =================
__global__ void embed_kernel(const int* __restrict__ ids, const float* __restrict__ emb,
                             const float* __restrict__ pos, float* __restrict__ x) {
    int idx = blockIdx.x * 256 + threadIdx.x;
    int row = idx >> 10;
    int c   = idx & 1023;
    int t   = row & (T_-1);
    x[idx] = emb[(size_t)ids[row]*D_ + c] + pos[(size_t)t*D_ + c];
}

// W [K,N] fp32 -> out [Npad,K] fp16 (transposed, zero-padded), batched over z
__global__ void wconv_kernel(const float* __restrict__ W, __half* __restrict__ oh,
                             int K, int N, long long srcStride, long long dstStride) {
    __shared__ float tile[32][33];
    const float* Ws = W + (size_t)blockIdx.z * srcStride;
    __half* ohz = oh + (size_t)blockIdx.z * dstStride;
    int n0 = blockIdx.x * 32, k0 = blockIdx.y * 32;
    #pragma unroll
    for (int j = 0; j < 32; j += 8) {
        int kk = k0 + threadIdx.y + j;
        int nn = n0 + threadIdx.x;
        tile[threadIdx.y + j][threadIdx.x] = (nn < N) ? Ws[(size_t)kk*N + nn] : 0.f;
    }
    __syncthreads();
    #pragma unroll
    for (int j = 0; j < 32; j += 8) {
        int nn = n0 + threadIdx.y + j;
        int kk = k0 + threadIdx.x;
        ohz[(size_t)nn*K + kk] = __float2half(tile[threadIdx.x][threadIdx.y + j]);
    }
}

// Wq/Wk/Wv [L][K,N] fp32 -> g_wqkv [L][3072,K] fp16, z in [0, 3L)
__global__ void wconv3_kernel(const float* __restrict__ Wq, const float* __restrict__ Wk,
                              const float* __restrict__ Wv, __half* __restrict__ dst) {
    __shared__ float tile[32][33];
    int z = blockIdx.z;
    int l = z / 3, sel = z % 3;
    const float* Ws = (sel == 0 ? Wq : sel == 1 ? Wk : Wv) + (size_t)l * D_ * D_;
    __half* od = dst + ((size_t)l * 3072 + sel * D_) * D_;
    int n0 = blockIdx.x * 32, k0 = blockIdx.y * 32;
    #pragma unroll
    for (int j = 0; j < 32; j += 8) {
        tile[threadIdx.y + j][threadIdx.x] = Ws[(size_t)(k0 + threadIdx.y + j)*D_ + n0 + threadIdx.x];
    }
    __syncthreads();
    #pragma unroll
    for (int j = 0; j < 32; j += 8) {
        int nn = n0 + threadIdx.y + j;
        int kk = k0 + threadIdx.x;
        od[(size_t)nn*D_ + kk] = __float2half(tile[threadIdx.x][threadIdx.y + j]);
    }
}

__global__ void rmsnorm_split_kernel(const float* __restrict__ x, const float* __restrict__ w,
                                     __half* __restrict__ oh, __half* __restrict__ ol) {
    __shared__ float red[256];
    int row = blockIdx.x;
    const float* xr = x + (size_t)row * D_;
    float v[4]; float ss = 0.f;
    #pragma unroll
    for (int i = 0; i < 4; i++) { v[i] = xr[threadIdx.x + 256*i]; ss += v[i]*v[i]; }
    red[threadIdx.x] = ss; __syncthreads();
    for (int s = 128; s > 0; s >>= 1) {
        if (threadIdx.x < s) red[threadIdx.x] += red[threadIdx.x + s];
        __syncthreads();
    }
    float r = rsqrtf(red[0] / (float)D_ + 1e-5f);
    #pragma unroll
    for (int i = 0; i < 4; i++) {
        int c = threadIdx.x + 256*i;
        float y = w[c] * v[i] * r;
        __half hi, lo; fp16_split(y, hi, lo);
        oh[(size_t)row*D_ + c] = hi;
        ol[(size_t)row*D_ + c] = lo;
    }
}

// RMS over head_dim + transpose [B,T,3D] -> [B,H,T,HD] fp16 (lo optional). One warp per (b,t,h).
__global__ void qknorm_split_kernel(const float* __restrict__ qkv, int colOff,
                                    const float* __restrict__ w,
                                    __half* __restrict__ qh, __half* __restrict__ ql) {
    int warp = (blockIdx.x * blockDim.x + threadIdx.x) >> 5;
    int lane = threadIdx.x & 31;
    int h  = warp & (H_-1);
    int bt = warp >> 4;
    int t  = bt & (T_-1);
    int b  = bt >> 10;
    const float* src = qkv + (size_t)bt * 3072 + colOff + h * HD_;
    float x0 = src[lane], x1 = src[lane + 32];
    float ss = x0*x0 + x1*x1;
    #pragma unroll
    for (int o = 16; o > 0; o >>= 1) ss += __shfl_xor_sync(0xffffffffu, ss, o);
    float r = rsqrtf(ss / (float)HD_ + 1e-5f);
    size_t dst = ((size_t)((b*H_ + h)*T_ + t)) * HD_;
    float y0 = w[lane] * x0 * r;
    float y1 = w[lane + 32] * x1 * r;
    __half h0 = __float2half(y0);
    __half h1 = __float2half(y1);
    qh[dst + lane]      = h0;
    qh[dst + lane + 32] = h1;
    if (ql) {
        ql[dst + lane]      = __float2half(y0 - __half2float(h0));
        ql[dst + lane + 32] = __float2half(y1 - __half2float(h1));
    }
}

// V: [B,T,3D](col 2048+) -> [B,H,HD,T] single fp16 via 32x32 tile transpose
__global__ void vtrans_kernel(const float* __restrict__ qkv, __half* __restrict__ vh) {
    __shared__ float tile[32][33];
    int z = blockIdx.z;           // b*H+h
    int b = z >> 4, h = z & 15;
    int t0 = blockIdx.x * 32, d0 = blockIdx.y * 32;
    #pragma unroll
    for (int j = 0; j < 32; j += 8) {
        int t = t0 + threadIdx.y + j;
        tile[threadIdx.y + j][threadIdx.x] =
            qkv[(size_t)(b*T_ + t)*3072 + 2048 + h*HD_ + d0 + threadIdx.x];
    }
    __syncthreads();
    #pragma unroll
    for (int j = 0; j < 32; j += 8) {
        int d = d0 + threadIdx.y + j;
        size_t o = ((size_t)z * HD_ + d) * T_ + t0 + threadIdx.x;
        vh[o] = __float2half(tile[threadIdx.x][threadIdx.y + j]);
    }
}

// causal softmax, scale 1/8, per-head gate; writes P as fp16 hi/lo (zero tail)
__global__ void softmax_kernel(const float* __restrict__ S, const float* __restrict__ gate,
                               __half* __restrict__ ph, __half* __restrict__ pl) {
    __shared__ float red[256];
    int row = blockIdx.x;
    int q = row & (T_-1);
    int h = (row >> 10) & (H_-1);
    const float* s = S + (size_t)row * T_;
    const float scale = 0.125f;
    float vals[4]; float m = -3.4e38f;
    #pragma unroll
    for (int i = 0; i < 4; i++) {
        int j = threadIdx.x + 256*i;
        float v = (j <= q) ? s[j] * scale : -3.4e38f;
        vals[i] = v; m = fmaxf(m, v);
    }
    red[threadIdx.x] = m; __syncthreads();
    for (int t = 128; t > 0; t >>= 1) {
        if (threadIdx.x < t) red[threadIdx.x] = fmaxf(red[threadIdx.x], red[threadIdx.x + t]);
        __syncthreads();
    }
    m = red[0]; __syncthreads();
    float sum = 0.f;
    #pragma unroll
    for (int i = 0; i < 4; i++) {
        int j = threadIdx.x + 256*i;
        float e = (j <= q) ? __expf(vals[i] - m) : 0.f;
        vals[i] = e; sum += e;
    }
    red[threadIdx.x] = sum; __syncthreads();
    for (int t = 128; t > 0; t >>= 1) {
        if (threadIdx.x < t) red[threadIdx.x] += red[threadIdx.x + t];
        __syncthreads();
    }
    float inv = gate[h] / red[0];
    #pragma unroll
    for (int i = 0; i < 4; i++) {
        int j = threadIdx.x + 256*i;
        float p = vals[i] * inv;
        __half hi, lo; fp16_split(p, hi, lo);
        ph[(size_t)row*T_ + j] = hi;
        pl[(size_t)row*T_ + j] = lo;
    }
}

// ================= HMMA fp16 2-term split GEMM =================
// C[M,N] = (Ah+Al)[M,K] @ Bh[N,K]^T, fp32 accumulators.
// 3-stage cp.async pipeline, one __syncthreads per 32-K chunk.
// MODE: 0 = fp32 store (guard n<Nout), 1 = +RES, 2 = GELU->fp16 split, 3 = PV merge->fp16 split
#define HG_ROWB 80

__device__ __forceinline__ void hg_ldm4(uint32_t addr, uint32_t* r) {
    asm volatile("ldmatrix.sync.aligned.m8n8.x4.shared.b16 {%0,%1,%2,%3}, [%4];"
        : "=r"(r[0]), "=r"(r[1]), "=r"(r[2]), "=r"(r[3]) : "r"(addr));
}
__device__ __forceinline__ void hg_mma(float* d, const uint32_t* a, uint32_t b0, uint32_t b1) {
    asm volatile("mma.sync.aligned.m16n8k16.row.col.f32.f16.f16.f32 "
        "{%0,%1,%2,%3}, {%4,%5,%6,%7}, {%8,%9}, {%0,%1,%2,%3};"
        : "+f"(d[0]), "+f"(d[1]), "+f"(d[2]), "+f"(d[3])
        : "r"(a[0]), "r"(a[1]), "r"(a[2]), "r"(a[3]), "r"(b0), "r"(b1));
}

template<int BM, int BN>
__device__ __forceinline__ void hg_load2(uint32_t stg,
    const __half* Ah, const __half* Al, const __half* Bh,
    int m0, int n0, int K, int k0, int tid)
{
    constexpr int CA = BM * 4;         // 16B chunks per A matrix
    constexpr int CB = BN * 4;
    constexpr int TOT = 2*CA + CB;
    #pragma unroll
    for (int p = 0; p < TOT/256; p++) {
        int c = tid + p * 256;
        const __half* base; int r0; uint32_t mo; int rr;
        if (c < CA)        { base = Ah; r0 = m0; mo = 0;            rr = c; }
        else if (c < 2*CA) { base = Al; r0 = m0; mo = BM*HG_ROWB;   rr = c - CA; }
        else               { base = Bh; r0 = n0; mo = 2*BM*HG_ROWB; rr = c - 2*CA; }
        int r = rr >> 2, kc = rr & 3;
        uint32_t so = stg + mo + r * HG_ROWB + kc * 16;
        const void* ga = (const void*)(base + (size_t)(r0 + r) * K + k0 + kc * 8);
        asm volatile("cp.async.cg.shared.global [%0], [%1], 16;\n" :: "r"(so), "l"(ga));
    }
    asm volatile("cp.async.commit_group;\n" ::: "memory");
}

template<int BM, int BN, int MODE, bool CSKIP, bool CKLIM>
__global__ __launch_bounds__(256, 2)
void hgemm2_kernel(const __half* __restrict__ Ah, const __half* __restrict__ Al,
                   const __half* __restrict__ Bh,
                   const float* __restrict__ AUX, float* __restrict__ C,
                   __half* __restrict__ Gh, __half* __restrict__ Gl,
                   int K, int Nout, int ldc,
                   long long sA, long long sB, long long sC)
{
    constexpr int MATA  = BM * HG_ROWB;
    constexpr int STAGE = (2*BM + BN) * HG_ROWB;
    constexpr int MI = BM / 64;        // 16-row A tiles per warp
    constexpr int NJ = BN / 16;        // 8-col accum groups per warp
    constexpr int NT = BN / 32;        // 16-row B tiles per warp

    extern __shared__ char dsm[];
    uint32_t sb = smem_u32(dsm);

    const int tid  = threadIdx.x;
    const int lane = tid & 31;
    const int wid  = tid >> 5;
    const int warpM = (wid & 3) * (BM/4);
    const int warpN = (wid >> 2) * (BN/2);

    const int m0 = blockIdx.y * BM;
    const int n0 = blockIdx.x * BN;
    if (CSKIP && n0 > m0 + BM - 1) return;

    const int z = blockIdx.z;
    Ah += (size_t)z * sA; Al += (size_t)z * sA;
    Bh += (size_t)z * sB;
    if (MODE == 0) C += (size_t)z * sC;

    const uint32_t aoff = (uint32_t)((lane & 15) * HG_ROWB + (lane >> 4) * 16);
    const uint32_t boff = (uint32_t)(((lane & 7) + ((lane >> 4) & 1) * 8) * HG_ROWB
                                     + ((lane >> 3) & 1) * 16);

    float acc[MI][NJ][4];
    #pragma unroll
    for (int i = 0; i < MI; i++)
        #pragma unroll
        for (int j = 0; j < NJ; j++)
            #pragma unroll
            for (int u = 0; u < 4; u++) acc[i][j][u] = 0.f;

    const int kend = CKLIM ? (K < m0 + BM ? K : m0 + BM) : K;
    const int nk = kend / 32;

    // preload chunks 0 and 1 (nk >= 2 for every launch in this model)
    hg_load2<BM,BN>(sb,          Ah, Al, Bh, m0, n0, K, 0,  tid);
    if (nk > 1)
        hg_load2<BM,BN>(sb + STAGE, Ah, Al, Bh, m0, n0, K, 32, tid);

    for (int it = 0; it < nk; it++) {
        int s = it % 3;
        // ensure chunk `it` arrived
        if (it + 1 < nk) {
            asm volatile("cp.async.wait_group 1;\n" ::: "memory");
        } else {
            asm volatile("cp.async.wait_group 0;\n" ::: "memory");
        }
        __syncthreads();   // all warps done reading stage (it+2)%3 (their iter it-1 compute)
        if (it + 2 < nk) {
            hg_load2<BM,BN>(sb + ((it + 2) % 3) * STAGE, Ah, Al, Bh, m0, n0, K, (it + 2) * 32, tid);
        }

        uint32_t st  = sb + s * STAGE;
        uint32_t sAh = st;
        uint32_t sAl = st + MATA;
        uint32_t sBh = st + 2*MATA;

        #pragma unroll
        for (int kq = 0; kq < 2; kq++) {
            uint32_t kb = kq * 32;
            uint32_t ah[MI][4], al[MI][4], bh[NT][4];
            #pragma unroll
            for (int mi = 0; mi < MI; mi++) {
                uint32_t rb = (uint32_t)((warpM + mi * 16) * HG_ROWB) + kb;
                hg_ldm4(sAh + rb + aoff, ah[mi]);
                hg_ldm4(sAl + rb + aoff, al[mi]);
            }
            #pragma unroll
            for (int nt = 0; nt < NT; nt++) {
                uint32_t rb = (uint32_t)((warpN + nt * 16) * HG_ROWB) + kb;
                hg_ldm4(sBh + rb + boff, bh[nt]);
            }
            #pragma unroll
            for (int mi = 0; mi < MI; mi++) {
                #pragma unroll
                for (int nj = 0; nj < NJ; nj++) {
                    uint32_t b0 = bh[nj >> 1][(nj & 1) * 2];
                    uint32_t b1 = bh[nj >> 1][(nj & 1) * 2 + 1];
                    hg_mma(acc[mi][nj], ah[mi], b0, b1);
                    hg_mma(acc[mi][nj], al[mi], b0, b1);
                }
            }
        }
    }

    // epilogue (register-only inputs; no sync needed)
    const int g = lane >> 2;
    const int tq = lane & 3;
    #pragma unroll
    for (int mi = 0; mi < MI; mi++) {
        int row0 = m0 + warpM + mi * 16 + g;
        int row1 = row0 + 8;
        #pragma unroll
        for (int nj = 0; nj < NJ; nj++) {
            int col = n0 + warpN + nj * 8 + tq * 2;
            float* a = acc[mi][nj];
            if (MODE == 1) {
                size_t o0 = (size_t)row0 * ldc + col;
                size_t o1 = (size_t)row1 * ldc + col;
                C[o0]     = a[0] + AUX[o0];
                C[o0 + 1] = a[1] + AUX[o0 + 1];
                C[o1]     = a[2] + AUX[o1];
                C[o1 + 1] = a[3] + AUX[o1 + 1];
            } else if (MODE == 2) {
                #pragma unroll
                for (int half = 0; half < 2; half++) {
                    int r = half ? row1 : row0;
                    float v0 = a[half * 2], v1 = a[half * 2 + 1];
                    float g0 = 0.5f * v0 * (1.0f + erff(v0 * 0.70710678118654752f));
                    float g1 = 0.5f * v1 * (1.0f + erff(v1 * 0.70710678118654752f));
                    __half h0, l0, h1, l1;
                    fp16_split(g0, h0, l0); fp16_split(g1, h1, l1);
                    __half2 hp; hp.x = h0; hp.y = h1;
                    __half2 lp; lp.x = l0; lp.y = l1;
                    size_t o = (size_t)r * ldc + col;
                    *(__half2*)&Gh[o] = hp;
                    *(__half2*)&Gl[o] = lp;
                }
            } else if (MODE == 3) {
                int b  = z >> 4, h = z & 15;
                #pragma unroll
                for (int half = 0; half < 2; half++) {
                    int q = half ? row1 : row0;
                    size_t vsrc = (size_t)(b*T_ + q)*3072 + 2048 + h*HD_ + col;
                    float v0 = a[half * 2]     + AUX[vsrc];
                    float v1 = a[half * 2 + 1] + AUX[vsrc + 1];
                    __half h0, l0, h1, l1;
                    fp16_split(v0, h0, l0); fp16_split(v1, h1, l1);
                    __half2 hp; hp.x = h0; hp.y = h1;
                    __half2 lp; lp.x = l0; lp.y = l1;
                    size_t o = (size_t)(b*T_ + q)*D_ + h*HD_ + col;
                    *(__half2*)&Gh[o] = hp;
                    *(__half2*)&Gl[o] = lp;
                }
            } else {
                if (col < Nout) {
                    C[(size_t)row0 * ldc + col] = a[0];
                    C[(size_t)row1 * ldc + col] = a[2];
                }
                if (col + 1 < Nout) {
                    C[(size_t)row0 * ldc + col + 1] = a[1];
                    C[(size_t)row1 * ldc + col + 1] = a[3];
                }
            }
        }
    }
}

// ================= launcher =================
extern "C" void kernel_launch(void* const* d_in, const int* in_sizes, int n_in,
                              void* d_out, int out_size) {
    const int*   ids   = (const int*)  d_in[0];
    const float* embed = (const float*)d_in[1];
    const float* pos   = (const float*)d_in[2];
    const float* Wq    = (const float*)d_in[3];
    const float* Wk    = (const float*)d_in[4];
    const float* Wv    = (const float*)d_in[5];
    const float* Wo    = (const float*)d_in[6];
    const float* ln1   = (const float*)d_in[7];
    const float* ln2   = (const float*)d_in[8];
    const float* qnw   = (const float*)d_in[9];
    const float* knw   = (const float*)d_in[10];
    const float* gate  = (const float*)d_in[11];
    const float* W1    = (const float*)d_in[12];
    const float* W2    = (const float*)d_in[13];
    const float* lnf   = (const float*)d_in[14];
    const float* Wlm   = (const float*)d_in[15];
    float* out = (float*)d_out;

    float *x,*qkv,*att;
    __half *hh,*hl,*obh,*obl,*mph,*mpl;
    __half *qTh,*qTl,*kTh,*vTh,*ph,*pl;
    __half *wqkv,*wo,*w1,*w2,*wlm;
    cudaGetSymbolAddress((void**)&x,   g_x);
    cudaGetSymbolAddress((void**)&qkv, g_qkv);
    cudaGetSymbolAddress((void**)&att, g_att);
    cudaGetSymbolAddress((void**)&hh,  g_hh);
    cudaGetSymbolAddress((void**)&hl,  g_hl);
    cudaGetSymbolAddress((void**)&obh, g_obh);
    cudaGetSymbolAddress((void**)&obl, g_obl);
    cudaGetSymbolAddress((void**)&mph, g_mph);
    cudaGetSymbolAddress((void**)&mpl, g_mpl);
    cudaGetSymbolAddress((void**)&qTh, g_qTh);
    cudaGetSymbolAddress((void**)&qTl, g_qTl);
    cudaGetSymbolAddress((void**)&kTh, g_kTh);
    cudaGetSymbolAddress((void**)&vTh, g_vTh);
    cudaGetSymbolAddress((void**)&ph,  g_ph);
    cudaGetSymbolAddress((void**)&pl,  g_pl);
    cudaGetSymbolAddress((void**)&wqkv, g_wqkv);
    cudaGetSymbolAddress((void**)&wo,  g_wo);
    cudaGetSymbolAddress((void**)&w1,  g_w1);
    cudaGetSymbolAddress((void**)&w2,  g_w2);
    cudaGetSymbolAddress((void**)&wlm, g_wlm);

    // 3-stage smem sizes
    const int S128128 = 3 * (2*128 + 128) * HG_ROWB;   // 92160
    const int S64128  = 3 * (2*64  + 128) * HG_ROWB;   // 61440
    const int S6464   = 3 * (2*64  + 64 ) * HG_ROWB;   // 46080
    cudaFuncSetAttribute(hgemm2_kernel<128,128,0,false,false>, cudaFuncAttributeMaxDynamicSharedMemorySize, S128128);
    cudaFuncSetAttribute(hgemm2_kernel<128,128,2,false,false>, cudaFuncAttributeMaxDynamicSharedMemorySize, S128128);
    cudaFuncSetAttribute(hgemm2_kernel<128,128,0,true, false>, cudaFuncAttributeMaxDynamicSharedMemorySize, S128128);
    cudaFuncSetAttribute(hgemm2_kernel<64,128,0,false,false>,  cudaFuncAttributeMaxDynamicSharedMemorySize, S64128);
    cudaFuncSetAttribute(hgemm2_kernel<64,128,1,false,false>,  cudaFuncAttributeMaxDynamicSharedMemorySize, S64128);
    cudaFuncSetAttribute(hgemm2_kernel<64, 64, 3,false,true >, cudaFuncAttributeMaxDynamicSharedMemorySize, S6464);

    const long long sQK = (long long)T_ * HD_;
    const long long sS  = (long long)T_ * T_;
    dim3 wb(32, 8);

    embed_kernel<<<BT_*D_/256, 256>>>(ids, embed, pos, x);
    rmsnorm_split_kernel<<<BT_, 256>>>(x, ln1, hh, hl);
    wconv3_kernel<<<dim3(D_/32, D_/32, 3*L_), wb>>>(Wq, Wk, Wv, wqkv);
    // fused QKV layer 0: 64x128 tiles -> 768 CTAs (better wave fill)
    hgemm2_kernel<64,128,0,false,false><<<dim3(3072/128, BT_/64), 256, S64128>>>(
        hh, hl, wqkv, nullptr, qkv, nullptr, nullptr, D_, 3072, 3072, 0, 0, 0);

    // remaining weight conversions
    wconv_kernel<<<dim3(D_/32, D_/32, L_), wb>>>(Wo, wo, D_, D_, (long long)D_*D_, (long long)D_*D_);
    wconv_kernel<<<dim3(F_/32, D_/32, L_), wb>>>(W1, w1, D_, F_, (long long)D_*F_, (long long)F_*D_);
    wconv_kernel<<<dim3(D_/32, F_/32, L_), wb>>>(W2, w2, F_, D_, (long long)F_*D_, (long long)D_*F_);
    wconv_kernel<<<dim3(VPAD_/32, D_/32, 1), wb>>>(Wlm, wlm, D_, V_, 0, 0);

    for (int l = 0; l < L_; l++) {
        qknorm_split_kernel<<<(B_*T_*H_)/8, 256>>>(qkv, 0,    qnw + (size_t)l*HD_, qTh, qTl);
        qknorm_split_kernel<<<(B_*T_*H_)/8, 256>>>(qkv, 1024, knw + (size_t)l*HD_, kTh, nullptr);
        vtrans_kernel<<<dim3(T_/32, HD_/32, B_*H_), dim3(32,8)>>>(qkv, vTh);

        // scores: per (b,h) Q[1024,64] @ K[1024,64]^T, causal tile-skip
        hgemm2_kernel<128,128,0,true,false><<<dim3(T_/128, T_/128, B_*H_), 256, S128128>>>(
            qTh, qTl, kTh, nullptr, att, nullptr, nullptr, HD_, T_, T_, sQK, sQK, sS);

        softmax_kernel<<<B_*H_*T_, 256>>>(att, gate + (size_t)l*H_, ph, pl);

        // PV: per (b,h) P[1024,1024] @ V^T, causal K-limit, fused vres merge+split
        hgemm2_kernel<64,64,3,false,true><<<dim3(1, T_/64, B_*H_), 256, S6464>>>(
            ph, pl, vTh, qkv, nullptr, obh, obl, T_, HD_, HD_, sS, sQK, 0);

        // Wo with fused residual into x: 64x128 -> 256 CTAs
        hgemm2_kernel<64,128,1,false,false><<<dim3(D_/128, BT_/64), 256, S64128>>>(
            obh, obl, wo + (size_t)l*D_*D_, x, x, nullptr, nullptr, D_, D_, D_, 0, 0, 0);

        // MLP
        rmsnorm_split_kernel<<<BT_, 256>>>(x, ln2 + (size_t)l*D_, hh, hl);
        hgemm2_kernel<128,128,2,false,false><<<dim3(F_/128, BT_/128), 256, S128128>>>(
            hh, hl, w1 + (size_t)l*F_*D_, nullptr, nullptr, mph, mpl, D_, F_, F_, 0, 0, 0);
        hgemm2_kernel<64,128,1,false,false><<<dim3(D_/128, BT_/64), 256, S64128>>>(
            mph, mpl, w2 + (size_t)l*D_*F_, x, x, nullptr, nullptr, F_, D_, D_, 0, 0, 0);

        // next layer's pre-attention norm + QKV
        if (l + 1 < L_) {
            rmsnorm_split_kernel<<<BT_, 256>>>(x, ln1 + (size_t)(l+1)*D_, hh, hl);
            hgemm2_kernel<64,128,0,false,false><<<dim3(3072/128, BT_/64), 256, S64128>>>(
                hh, hl, wqkv + (size_t)(l+1)*3072*D_, nullptr, qkv, nullptr, nullptr,
                D_, 3072, 3072, 0, 0, 0);
        }
    }

    rmsnorm_split_kernel<<<BT_, 256>>>(x, lnf, hh, hl);
    hgemm2_kernel<128,128,0,false,false><<<dim3(VPAD_/128, BT_/128), 256, S128128>>>(
        hh, hl, wlm, nullptr, out, nullptr, nullptr, D_, V_, V_, 0, 0, 0);
}